// round 10
// baseline (speedup 1.0000x reference)
#include <cuda_runtime.h>

// NaturalCubicSplinePotential — GB300 sm_103a
//
// R8: latency attack. R7 showed the kernel is latency-exposed (wall 33us vs
// L1-busy ~17us) and that squeezing regs to 32 for a 7th CTA collapsed MLP.
// This round: __launch_bounds__(256,6) -> 42-reg budget, fully unrolled main
// loop with explicit 2-deep load pipeline (next 2 float4 loads issued before
// evaluating current 2) -> front-batched LDG + 8 independent eval chains per
// stage to overlap the 29-cyc LDS latency.
//
// Verified-kept: conflict-free float4/NSLOT=8 slotted gather, TABN=224
// (PADL=48 covers |x|<=7), closed-form [1,4,1] inverse (31-tap conv),
// magic-number floor + midpoint recentering, fused deterministic last-block
// reduction.

#define NM 8
#define NN 128
#define TABN 224
#define PADL 48
#define NSLOT 8
#define EVAL_BLOCKS 1024
#define F4_PER_BLOCK 4096
#define NTHREADS 256
#define ITERS (F4_PER_BLOCK / NTHREADS)   // 16
#define CONV_R 15

__device__ float g_part[EVAL_BLOCKS];
__device__ unsigned int g_ticket;   // zero-init; self-resets each call

#define LOG2_LAM 1.89996863f        // log2(2+sqrt(3))
#define INV_D0   1.07735027f        // 1/(1-lam^-2)
#define MAGIC    12582912.0f        // 1.5 * 2^23
#define MAGIC_I  0x4B400000

// ---------------------------------------------------------------------------
__device__ __forceinline__ void eval_lane(float xv, const float4* __restrict__ tslot,
                                          float& acc)
{
    // t = (x+4)*15.875 + 48 (pad), midpoint-shifted: t5 = x*15.875 + 111.0
    const float t5 = __fmaf_rn(xv, 15.875f, 111.0f);
    const float tm = t5 + MAGIC;                    // round(t5) == floor(t) a.e.
    const int   i  = __float_as_int(tm) - MAGIC_I;
    const float v  = t5 - (tm - MAGIC);             // v = u - 0.5 in [-0.5,0.5)
    const float4 cf = tslot[i * NSLOT];             // conflict-free slot gather
    acc += __fmaf_rn(v, __fmaf_rn(v, __fmaf_rn(v, cf.w, cf.z), cf.y), cf.x);
}

__global__ void __launch_bounds__(NTHREADS, 6)
eval_kernel(const float4* __restrict__ x4,
            const float* __restrict__ nodal,
            float* __restrict__ out)
{
    __shared__ float4 tab[TABN * NSLOT];                // 28 KB, lane-slotted
    __shared__ float  ysh[NN];
    __shared__ float  pw[256];                          // pw[k] = lam^{-k}
    __shared__ float  srsh[NN + 2 * (CONV_R + 1)];      // padded (-1)^j * r_j
    __shared__ float  csh[NN];
    __shared__ float  wsum[NTHREADS / 32];
    __shared__ bool   amLast;

    const int tid = threadIdx.x;
    // slab (bs,f) = 65536 elems = 4 blocks; marginal index = slab & 7
    const int m = (blockIdx.x >> 2) & 7;

    // ---- prologue: closed-form spline solve --------------------------------
    if (tid < NN)
        ysh[tid] = nodal[m * NN + tid];
    pw[tid] = exp2f(-LOG2_LAM * (float)tid);
    if (tid < NN + 2 * (CONV_R + 1))
        srsh[tid] = 0.0f;
    __syncthreads();

    const float inv_h2 = (127.0f / 8.0f) * (127.0f / 8.0f);
    if (tid >= 1 && tid <= 126) {
        float r = 3.0f * (ysh[tid - 1] - 2.0f * ysh[tid] + ysh[tid + 1]) * inv_h2;
        srsh[(CONV_R + 1) + tid] = (tid & 1) ? -r : r;
    }
    __syncthreads();

    if (tid < NN) {
        const int i = tid;
        float c = 0.0f;
        if (i >= 1 && i <= 126) {
#pragma unroll
            for (int dj = -CONV_R; dj <= CONV_R; ++dj) {
                const int j  = i + dj;
                const int jc = min(max(j, 1), 126);
                const int mi = min(i, jc);
                const int mx = max(i, jc);
                const float w = pw[(dj < 0 ? -dj : dj) + 1]
                              * (1.0f - pw[2 * mi])
                              * (1.0f - pw[2 * (127 - mx)]);
                c = __fmaf_rn(w, srsh[(CONV_R + 1) + j], c);
            }
            c *= INV_D0;
            if (i & 1) c = -c;
        }
        csh[i] = c;
    }
    __syncthreads();

    // ---- padded + midpoint-recentered table, 8 slots -----------------------
    if (tid < TABN) {
        const float h  = 8.0f / 127.0f;
        const float h2 = h * h;
        const int j  = tid;
        const int it = j - PADL;
        const int k  = min(max(it, 0), 126);
        const float s = (float)(it - k) + 0.5f;     // shift incl. midpoint

        const float A  = ysh[k];
        const float c0 = csh[k];
        const float c1 = csh[k + 1];
        const float B  = (ysh[k + 1] - A) - h2 * (2.0f * c0 + c1) * (1.0f / 3.0f);
        const float C  = c0 * h2;
        const float D  = (c1 - c0) * h2 * (1.0f / 3.0f);

        const float4 cf = make_float4(A + s * (B + s * (C + s * D)),
                                      B + s * (2.0f * C + 3.0f * D * s),
                                      C + 3.0f * D * s,
                                      D);
#pragma unroll
        for (int sl = 0; sl < NSLOT; ++sl)
            tab[j * NSLOT + sl] = cf;
    }
    __syncthreads();

    // ---- main evaluation loop: 2-deep software pipeline --------------------
    const float4* tslot = tab + (tid & 7);          // this lane's bank-quad
    const float4* p = x4 + (size_t)blockIdx.x * F4_PER_BLOCK + tid;

    float a0 = 0.0f, a1 = 0.0f, a2 = 0.0f, a3 = 0.0f;

    float4 b0 = p[0];
    float4 b1 = p[NTHREADS];
#pragma unroll
    for (int it = 0; it < ITERS; it += 2) {
        const float4 v0 = b0;
        const float4 v1 = b1;
        if (it + 2 < ITERS) {                       // compile-time resolved
            b0 = p[(it + 2) * NTHREADS];
            b1 = p[(it + 3) * NTHREADS];
        }
        eval_lane(v0.x, tslot, a0);
        eval_lane(v0.y, tslot, a1);
        eval_lane(v0.z, tslot, a2);
        eval_lane(v0.w, tslot, a3);
        eval_lane(v1.x, tslot, a0);
        eval_lane(v1.y, tslot, a1);
        eval_lane(v1.z, tslot, a2);
        eval_lane(v1.w, tslot, a3);
    }

    float s = (a0 + a1) + (a2 + a3);
#pragma unroll
    for (int o = 16; o > 0; o >>= 1)
        s += __shfl_xor_sync(0xFFFFFFFFu, s, o);

    if ((tid & 31) == 0)
        wsum[tid >> 5] = s;
    __syncthreads();

    if (tid == 0) {
        float t = 0.0f;
#pragma unroll
        for (int w = 0; w < NTHREADS / 32; ++w)
            t += wsum[w];
        g_part[blockIdx.x] = t;
        __threadfence();
        const unsigned int ticket = atomicAdd(&g_ticket, 1u);
        amLast = (ticket == EVAL_BLOCKS - 1);
    }
    __syncthreads();

    // ---- last block: deterministic fixed-order final reduction -------------
    if (amLast) {
        __threadfence();
        float r = 0.0f;
#pragma unroll
        for (int i = 0; i < EVAL_BLOCKS / NTHREADS; ++i)
            r += g_part[tid + i * NTHREADS];

        __shared__ float sh[NTHREADS];
        sh[tid] = r;
        __syncthreads();
#pragma unroll
        for (int st = NTHREADS / 2; st > 0; st >>= 1) {
            if (tid < st)
                sh[tid] += sh[tid + st];
            __syncthreads();
        }
        if (tid == 0) {
            out[0] = sh[0];
            g_ticket = 0u;   // reset for next call / graph replay
        }
    }
}

// ---------------------------------------------------------------------------
extern "C" void kernel_launch(void* const* d_in, const int* in_sizes, int n_in,
                              void* d_out, int out_size)
{
    const float* x     = (const float*)d_in[0];        // (32,8,256,256) fp32
    const float* nodal = (const float*)d_in[1];        // (8,128) fp32
    float* out = (float*)d_out;

    eval_kernel<<<EVAL_BLOCKS, NTHREADS>>>((const float4*)x, nodal, out);
}

// round 11
// speedup vs baseline: 1.1486x; 1.1486x over previous
#include <cuda_runtime.h>

// NaturalCubicSplinePotential — GB300 sm_103a
//
// R10: eliminate the 2nd-wave tail WITHOUT sacrificing registers.
// R5-geometry (6 CTAs/SM, 40 regs) leaves 136 of 1024 blocks in a straggler
// wave. New grid = 888 = 148x6 (exact single wave); the extra 136 chunks are
// statically assigned to distinct blocks whose own chunk has the SAME marginal
// (chunk offsets +128/+256/+384 are 0 mod 32 -> marginal preserved), so the
// already-built table is reused and per-SM load stays balanced:
//   blocks 504-511  -> second chunk b+384  (chunks 888-895)
//   blocks 768-887  -> second chunk b+128  (chunks 896-1015)
//   blocks 760-767  -> second chunk b+256  (chunks 1016-1023)
//
// Verified-kept: conflict-free float4/NSLOT=8 slotted gather (LDS.128 ~8.3cyc,
// measured floor), TABN=224 (PADL=48 covers |x|<=7), closed-form [1,4,1]
// inverse (31-tap conv), magic floor + midpoint recentering, R5's simple
// unroll-4 loop (ptxas schedules it best), fused deterministic reduction.

#define NM 8
#define NN 128
#define TABN 224
#define PADL 48
#define NSLOT 8
#define EVAL_BLOCKS 888
#define F4_PER_CHUNK 4096          // 16384 elements per chunk
#define NTHREADS 256
#define CONV_R 15

__device__ float g_part[EVAL_BLOCKS];
__device__ unsigned int g_ticket;   // zero-init; self-resets each call

#define LOG2_LAM 1.89996863f        // log2(2+sqrt(3))
#define INV_D0   1.07735027f        // 1/(1-lam^-2)
#define MAGIC    12582912.0f        // 1.5 * 2^23
#define MAGIC_I  0x4B400000

// ---------------------------------------------------------------------------
__device__ __forceinline__ void eval_lane(float xv, const float4* __restrict__ tslot,
                                          float& acc)
{
    // t = (x+4)*15.875 + 48 (pad), midpoint-shifted: t5 = x*15.875 + 111.0
    const float t5 = __fmaf_rn(xv, 15.875f, 111.0f);
    const float tm = t5 + MAGIC;                    // round(t5) == floor(t) a.e.
    const int   i  = __float_as_int(tm) - MAGIC_I;
    const float v  = t5 - (tm - MAGIC);             // v = u - 0.5 in [-0.5,0.5)
    const float4 cf = tslot[i * NSLOT];             // conflict-free slot gather
    acc += __fmaf_rn(v, __fmaf_rn(v, __fmaf_rn(v, cf.w, cf.z), cf.y), cf.x);
}

__device__ __forceinline__ void eval_chunk(const float4* __restrict__ x4, int chunk,
                                           int tid, const float4* __restrict__ tslot,
                                           float& a0, float& a1, float& a2, float& a3)
{
    const float4* p = x4 + (size_t)chunk * F4_PER_CHUNK + tid;
#pragma unroll 4
    for (int it = 0; it < F4_PER_CHUNK / NTHREADS; ++it) {
        const float4 v = p[it * NTHREADS];
        eval_lane(v.x, tslot, a0);
        eval_lane(v.y, tslot, a1);
        eval_lane(v.z, tslot, a2);
        eval_lane(v.w, tslot, a3);
    }
}

__global__ void __launch_bounds__(NTHREADS, 6)
eval_kernel(const float4* __restrict__ x4,
            const float* __restrict__ nodal,
            float* __restrict__ out)
{
    __shared__ float4 tab[TABN * NSLOT];                // 28 KB, lane-slotted
    __shared__ float  ysh[NN];
    __shared__ float  pw[256];                          // pw[k] = lam^{-k}
    __shared__ float  srsh[NN + 2 * (CONV_R + 1)];      // padded (-1)^j * r_j
    __shared__ float  csh[NN];
    __shared__ float  wsum[NTHREADS / 32];
    __shared__ bool   amLast;

    const int tid = threadIdx.x;
    const int b   = blockIdx.x;

    // second chunk (same marginal as chunk b, or -1)
    int chunk1 = -1;
    if (b >= 504 && b < 512)      chunk1 = b + 384;   // 888..895
    else if (b >= 768 && b < 888) chunk1 = b + 128;   // 896..1015
    else if (b >= 760 && b < 768) chunk1 = b + 256;   // 1016..1023

    // marginal: chunk = 4 per (bs,f) slab; marginal = (chunk>>2) & 7
    const int m = (b >> 2) & 7;

    // ---- prologue: closed-form spline solve --------------------------------
    if (tid < NN)
        ysh[tid] = nodal[m * NN + tid];
    pw[tid] = exp2f(-LOG2_LAM * (float)tid);
    if (tid < NN + 2 * (CONV_R + 1))
        srsh[tid] = 0.0f;
    __syncthreads();

    const float inv_h2 = (127.0f / 8.0f) * (127.0f / 8.0f);
    if (tid >= 1 && tid <= 126) {
        float r = 3.0f * (ysh[tid - 1] - 2.0f * ysh[tid] + ysh[tid + 1]) * inv_h2;
        srsh[(CONV_R + 1) + tid] = (tid & 1) ? -r : r;
    }
    __syncthreads();

    if (tid < NN) {
        const int i = tid;
        float c = 0.0f;
        if (i >= 1 && i <= 126) {
#pragma unroll
            for (int dj = -CONV_R; dj <= CONV_R; ++dj) {
                const int j  = i + dj;
                const int jc = min(max(j, 1), 126);
                const int mi = min(i, jc);
                const int mx = max(i, jc);
                const float w = pw[(dj < 0 ? -dj : dj) + 1]
                              * (1.0f - pw[2 * mi])
                              * (1.0f - pw[2 * (127 - mx)]);
                c = __fmaf_rn(w, srsh[(CONV_R + 1) + j], c);
            }
            c *= INV_D0;
            if (i & 1) c = -c;
        }
        csh[i] = c;
    }
    __syncthreads();

    // ---- padded + midpoint-recentered table, 8 slots -----------------------
    if (tid < TABN) {
        const float h  = 8.0f / 127.0f;
        const float h2 = h * h;
        const int j  = tid;
        const int it = j - PADL;
        const int k  = min(max(it, 0), 126);
        const float s = (float)(it - k) + 0.5f;     // shift incl. midpoint

        const float A  = ysh[k];
        const float c0 = csh[k];
        const float c1 = csh[k + 1];
        const float B  = (ysh[k + 1] - A) - h2 * (2.0f * c0 + c1) * (1.0f / 3.0f);
        const float C  = c0 * h2;
        const float D  = (c1 - c0) * h2 * (1.0f / 3.0f);

        const float4 cf = make_float4(A + s * (B + s * (C + s * D)),
                                      B + s * (2.0f * C + 3.0f * D * s),
                                      C + 3.0f * D * s,
                                      D);
#pragma unroll
        for (int sl = 0; sl < NSLOT; ++sl)
            tab[j * NSLOT + sl] = cf;
    }
    __syncthreads();

    // ---- main evaluation: 1 or 2 same-marginal chunks ----------------------
    const float4* tslot = tab + (tid & 7);          // this lane's bank-quad

    float a0 = 0.0f, a1 = 0.0f, a2 = 0.0f, a3 = 0.0f;
    eval_chunk(x4, b, tid, tslot, a0, a1, a2, a3);
    if (chunk1 >= 0)
        eval_chunk(x4, chunk1, tid, tslot, a0, a1, a2, a3);

    float s = (a0 + a1) + (a2 + a3);
#pragma unroll
    for (int o = 16; o > 0; o >>= 1)
        s += __shfl_xor_sync(0xFFFFFFFFu, s, o);

    if ((tid & 31) == 0)
        wsum[tid >> 5] = s;
    __syncthreads();

    if (tid == 0) {
        float t = 0.0f;
#pragma unroll
        for (int w = 0; w < NTHREADS / 32; ++w)
            t += wsum[w];
        g_part[b] = t;
        __threadfence();
        const unsigned int ticket = atomicAdd(&g_ticket, 1u);
        amLast = (ticket == EVAL_BLOCKS - 1);
    }
    __syncthreads();

    // ---- last block: deterministic fixed-order final reduction -------------
    if (amLast) {
        __threadfence();
        float r = 0.0f;
#pragma unroll
        for (int i = 0; i < 4; ++i) {
            const int idx = tid + i * NTHREADS;
            if (idx < EVAL_BLOCKS)
                r += g_part[idx];
        }

        __shared__ float sh[NTHREADS];
        sh[tid] = r;
        __syncthreads();
#pragma unroll
        for (int st = NTHREADS / 2; st > 0; st >>= 1) {
            if (tid < st)
                sh[tid] += sh[tid + st];
            __syncthreads();
        }
        if (tid == 0) {
            out[0] = sh[0];
            g_ticket = 0u;   // reset for next call / graph replay
        }
    }
}

// ---------------------------------------------------------------------------
extern "C" void kernel_launch(void* const* d_in, const int* in_sizes, int n_in,
                              void* d_out, int out_size)
{
    const float* x     = (const float*)d_in[0];        // (32,8,256,256) fp32
    const float* nodal = (const float*)d_in[1];        // (8,128) fp32
    float* out = (float*)d_out;

    eval_kernel<<<EVAL_BLOCKS, NTHREADS>>>((const float4*)x, nodal, out);
}